// round 5
// baseline (speedup 1.0000x reference)
#include <cuda_runtime.h>
#include <cuda_bf16.h>
#include <cstdint>

#define VOCAB 50000
#define DMODEL 256
#define NCELLS (4 * 64 * 64)   // 16384
#define NTOK 32
#define TABLE_BYTES (VOCAB * 4)   // 200000, multiple of 16

__device__ float g_proj[VOCAB];

// ---------------------------------------------------------------------------
// Kernel 1: p[v] = dot(E[v,:], W). One warp per FOUR vocab rows
// (8 outstanding LDG.128/thread). Chip-L2 streaming bound (~4 us floor).
// Signals dependent launch (PDL) after its stores.
// ---------------------------------------------------------------------------
__global__ void __launch_bounds__(256) proj_kernel(
    const float* __restrict__ E,
    const float* __restrict__ W)
{
    int gwarp = (blockIdx.x * blockDim.x + threadIdx.x) >> 5;
    int lane  = threadIdx.x & 31;
    int row0  = gwarp * 4;

    if (row0 < VOCAB) {
        const float4* __restrict__ e4 = reinterpret_cast<const float4*>(E);
        const float4* __restrict__ w4 = reinterpret_cast<const float4*>(W);

        float4 wa = w4[lane];
        float4 wb = w4[lane + 32];

        float4 r0a = e4[(size_t)(row0 + 0) * 64 + lane];
        float4 r0b = e4[(size_t)(row0 + 0) * 64 + lane + 32];
        float4 r1a = e4[(size_t)(row0 + 1) * 64 + lane];
        float4 r1b = e4[(size_t)(row0 + 1) * 64 + lane + 32];
        float4 r2a = e4[(size_t)(row0 + 2) * 64 + lane];
        float4 r2b = e4[(size_t)(row0 + 2) * 64 + lane + 32];
        float4 r3a = e4[(size_t)(row0 + 3) * 64 + lane];
        float4 r3b = e4[(size_t)(row0 + 3) * 64 + lane + 32];

        float s0 = 0.f, s1 = 0.f, s2 = 0.f, s3 = 0.f;
        s0 = fmaf(r0a.x, wa.x, s0); s0 = fmaf(r0a.y, wa.y, s0);
        s0 = fmaf(r0a.z, wa.z, s0); s0 = fmaf(r0a.w, wa.w, s0);
        s0 = fmaf(r0b.x, wb.x, s0); s0 = fmaf(r0b.y, wb.y, s0);
        s0 = fmaf(r0b.z, wb.z, s0); s0 = fmaf(r0b.w, wb.w, s0);

        s1 = fmaf(r1a.x, wa.x, s1); s1 = fmaf(r1a.y, wa.y, s1);
        s1 = fmaf(r1a.z, wa.z, s1); s1 = fmaf(r1a.w, wa.w, s1);
        s1 = fmaf(r1b.x, wb.x, s1); s1 = fmaf(r1b.y, wb.y, s1);
        s1 = fmaf(r1b.z, wb.z, s1); s1 = fmaf(r1b.w, wb.w, s1);

        s2 = fmaf(r2a.x, wa.x, s2); s2 = fmaf(r2a.y, wa.y, s2);
        s2 = fmaf(r2a.z, wa.z, s2); s2 = fmaf(r2a.w, wa.w, s2);
        s2 = fmaf(r2b.x, wb.x, s2); s2 = fmaf(r2b.y, wb.y, s2);
        s2 = fmaf(r2b.z, wb.z, s2); s2 = fmaf(r2b.w, wb.w, s2);

        s3 = fmaf(r3a.x, wa.x, s3); s3 = fmaf(r3a.y, wa.y, s3);
        s3 = fmaf(r3a.z, wa.z, s3); s3 = fmaf(r3a.w, wa.w, s3);
        s3 = fmaf(r3b.x, wb.x, s3); s3 = fmaf(r3b.y, wb.y, s3);
        s3 = fmaf(r3b.z, wb.z, s3); s3 = fmaf(r3b.w, wb.w, s3);

        #pragma unroll
        for (int o = 16; o > 0; o >>= 1) {
            s0 += __shfl_xor_sync(0xFFFFFFFFu, s0, o);
            s1 += __shfl_xor_sync(0xFFFFFFFFu, s1, o);
            s2 += __shfl_xor_sync(0xFFFFFFFFu, s2, o);
            s3 += __shfl_xor_sync(0xFFFFFFFFu, s3, o);
        }
        if (lane == 0) {
            g_proj[row0 + 0] = s0;
            g_proj[row0 + 1] = s1;
            g_proj[row0 + 2] = s2;
            g_proj[row0 + 3] = s3;
        }
    }

    // Allow the dependent gather kernel's prolog to start on freed SMs.
    asm volatile("griddepcontrol.launch_dependents;" ::: "memory");
}

// ---------------------------------------------------------------------------
// Kernel 2: out[cell] = sum_t p[x[cell,t]] + bias.
// 128 blocks x 1024 threads. PDL prolog: x int4 + bias loaded BEFORE
// griddepcontrol.wait (overlaps proj's tail). Table fill: 4 cp.async.bulk
// (TMA) of 50000 B each into one mbarrier -> no LDGSTS issue cost, no L1tex
// queue. Then LDS gathers (conflict-degree cost only) + 8-lane reduce.
// ---------------------------------------------------------------------------
__global__ void __launch_bounds__(1024) gather_kernel(
    const int* __restrict__ x,
    const float* __restrict__ bias,
    float* __restrict__ out)
{
    extern __shared__ float s_proj[];          // 200000 B
    __shared__ __align__(8) uint64_t mbar;

    int tid  = threadIdx.x;
    int lane = tid & 31;
    int wid  = tid >> 5;
    int gw   = blockIdx.x * 32 + wid;          // cell-quad id, 0..4095

    // ---- prolog: independent of proj's output ----
    int4 t   = reinterpret_cast<const int4*>(x)[gw * 32 + lane];
    float bv = bias[0];

    uint32_t mbar_addr = (uint32_t)__cvta_generic_to_shared(&mbar);
    if (tid == 0) {
        asm volatile("mbarrier.init.shared.b64 [%0], 1;" :: "r"(mbar_addr) : "memory");
    }
    __syncthreads();

    // ---- wait for proj's memory to be visible ----
    asm volatile("griddepcontrol.wait;" ::: "memory");

    // ---- TMA bulk fill of the table ----
    if (tid == 0) {
        asm volatile("mbarrier.arrive.expect_tx.shared.b64 _, [%0], %1;"
                     :: "r"(mbar_addr), "r"((uint32_t)TABLE_BYTES) : "memory");
        uint32_t sdst = (uint32_t)__cvta_generic_to_shared(s_proj);
        const char* src = reinterpret_cast<const char*>(g_proj);
        #pragma unroll
        for (int c = 0; c < 4; ++c) {
            asm volatile(
                "cp.async.bulk.shared::cta.global.mbarrier::complete_tx::bytes "
                "[%0], [%1], %2, [%3];"
                :: "r"(sdst + c * (TABLE_BYTES / 4)),
                   "l"(src + c * (TABLE_BYTES / 4)),
                   "r"((uint32_t)(TABLE_BYTES / 4)),
                   "r"(mbar_addr)
                : "memory");
        }
    }

    // All threads wait on the mbarrier (phase 0)
    {
        uint32_t done;
        asm volatile(
            "{\n\t"
            ".reg .pred p;\n\t"
            "mbarrier.try_wait.parity.acquire.cta.shared::cta.b64 p, [%1], 0;\n\t"
            "selp.b32 %0, 1, 0, p;\n\t"
            "}"
            : "=r"(done) : "r"(mbar_addr) : "memory");
        if (!done) {
            asm volatile(
                "{\n\t"
                ".reg .pred P1;\n\t"
                "WAIT_LOOP_%=:\n\t"
                "mbarrier.try_wait.parity.acquire.cta.shared::cta.b64 P1, [%0], 0, 0x989680;\n\t"
                "@P1 bra.uni WAIT_DONE_%=;\n\t"
                "bra.uni WAIT_LOOP_%=;\n\t"
                "WAIT_DONE_%=:\n\t"
                "}"
                :: "r"(mbar_addr) : "memory");
        }
    }

    // ---- gather + reduce ----
    float s = s_proj[t.x] + s_proj[t.y] + s_proj[t.z] + s_proj[t.w];

    s += __shfl_xor_sync(0xFFFFFFFFu, s, 4);
    s += __shfl_xor_sync(0xFFFFFFFFu, s, 2);
    s += __shfl_xor_sync(0xFFFFFFFFu, s, 1);

    if ((lane & 7) == 0) out[gw * 4 + (lane >> 3)] = s + bv;
}

extern "C" void kernel_launch(void* const* d_in, const int* in_sizes, int n_in,
                              void* d_out, int out_size)
{
    const int*   x = (const int*)  d_in[0];
    const float* E = (const float*)d_in[1];
    const float* W = (const float*)d_in[2];
    const float* b = (const float*)d_in[3];
    float* out = (float*)d_out;

    static bool attr_done = false;
    if (!attr_done) {
        cudaFuncSetAttribute(gather_kernel,
                             cudaFuncAttributeMaxDynamicSharedMemorySize,
                             TABLE_BYTES);
        attr_done = true;
    }

    // proj: 12500 warps (4 rows each) -> 1563 blocks of 256
    proj_kernel<<<(VOCAB / 4 + 7) / 8, 256>>>(E, W);

    // gather: 128 blocks x 1024 threads, launched with programmatic stream
    // serialization so its prolog overlaps proj's tail wave.
    cudaLaunchConfig_t cfg = {};
    cfg.gridDim          = dim3(128, 1, 1);
    cfg.blockDim         = dim3(1024, 1, 1);
    cfg.dynamicSmemBytes = TABLE_BYTES;
    cfg.stream           = 0;
    cudaLaunchAttribute attrs[1];
    attrs[0].id = cudaLaunchAttributeProgrammaticStreamSerialization;
    attrs[0].val.programmaticStreamSerializationAllowed = 1;
    cfg.attrs    = attrs;
    cfg.numAttrs = 1;
    cudaLaunchKernelEx(&cfg, gather_kernel, x, b, out);
}